// round 4
// baseline (speedup 1.0000x reference)
#include <cuda_runtime.h>
#include <math.h>
#include <stdint.h>

#define N_G 50000
#define E_G 800000
#define N_S 10000
#define E_S 160000
#define NF 64
#define NB 8

// ---------------------------------------------------------------------------
// Scratch (device globals; allocation-free)
// ---------------------------------------------------------------------------
__device__ float g_buf0[(size_t)N_G * 256];
__device__ float g_buf1[(size_t)N_G * 256];
__device__ float g_agg [(size_t)N_G * 256];
__device__ float g_pool[2 * NB * 192];
__device__ float g_cnt [2 * NB];
__device__ int   g_rowptr[N_G + 1];
__device__ int   g_cursor[N_G];
__device__ int   g_srcs  [E_G];
__device__ int   g_bsums [512];

// ---------------------------------------------------------------------------
// CSR build: histogram -> 2-level exclusive scan -> cursor fill
// ---------------------------------------------------------------------------
__global__ void hist_kernel(const int* __restrict__ dst, int* __restrict__ counts, int E)
{
    int e = blockIdx.x * blockDim.x + threadIdx.x;
    if (e < E) atomicAdd(&counts[dst[e]], 1);
}

__global__ void scan1_kernel(const int* __restrict__ counts, int* __restrict__ bsums, int N)
{
    __shared__ int s[256];
    int i = blockIdx.x * 256 + threadIdx.x;
    int v = (i < N) ? counts[i] : 0;
    s[threadIdx.x] = v;
    __syncthreads();
    for (int off = 128; off > 0; off >>= 1) {
        if (threadIdx.x < off) s[threadIdx.x] += s[threadIdx.x + off];
        __syncthreads();
    }
    if (threadIdx.x == 0) bsums[blockIdx.x] = s[0];
}

__global__ void scan2_kernel(int* __restrict__ bsums, int nb, int* __restrict__ rowptr,
                             int N, int E)
{
    __shared__ int s[256];
    int tid = threadIdx.x;
    int v = (tid < nb) ? bsums[tid] : 0;
    s[tid] = v;
    __syncthreads();
    for (int off = 1; off < 256; off <<= 1) {
        int t = (tid >= off) ? s[tid - off] : 0;
        __syncthreads();
        s[tid] += t;
        __syncthreads();
    }
    if (tid < nb) bsums[tid] = s[tid] - v;
    if (tid == 0) rowptr[N] = E;
}

__global__ void scan3_kernel(int* __restrict__ rowptr, const int* __restrict__ bsums,
                             int* __restrict__ cursor, int N)
{
    __shared__ int s[256];
    int tid = threadIdx.x;
    int i = blockIdx.x * 256 + tid;
    int v = (i < N) ? rowptr[i] : 0;
    s[tid] = v;
    __syncthreads();
    for (int off = 1; off < 256; off <<= 1) {
        int t = (tid >= off) ? s[tid - off] : 0;
        __syncthreads();
        s[tid] += t;
        __syncthreads();
    }
    if (i < N) {
        int val = s[tid] - v + bsums[blockIdx.x];
        rowptr[i] = val;
        cursor[i] = val;
    }
}

__global__ void fill_kernel(const int* __restrict__ src, const int* __restrict__ dst,
                            int* __restrict__ cursor, int* __restrict__ srcs, int E)
{
    int e = blockIdx.x * blockDim.x + threadIdx.x;
    if (e >= E) return;
    int d = dst[e];
    int p = atomicAdd(&cursor[d], 1);
    srcs[p] = src[e];
}

// ---------------------------------------------------------------------------
// CSR gather aggregation (float4, 4-way unroll)
// ---------------------------------------------------------------------------
__global__ __launch_bounds__(256)
void gather_kernel(const float4* __restrict__ x4, const int* __restrict__ rowptr,
                   const int* __restrict__ srcs, float4* __restrict__ agg4,
                   int N, int C4, int lgC4)
{
    int c    = threadIdx.x & (C4 - 1);
    int node = blockIdx.x * (256 >> lgC4) + (threadIdx.x >> lgC4);
    if (node >= N) return;
    int b = rowptr[node];
    int e = rowptr[node + 1];
    float4 a0 = make_float4(0.f, 0.f, 0.f, 0.f);
    float4 a1 = a0, a2 = a0, a3 = a0;
    int i = b;
    for (; i + 4 <= e; i += 4) {
        int s0 = srcs[i], s1 = srcs[i + 1], s2 = srcs[i + 2], s3 = srcs[i + 3];
        float4 v0 = x4[(size_t)s0 * C4 + c];
        float4 v1 = x4[(size_t)s1 * C4 + c];
        float4 v2 = x4[(size_t)s2 * C4 + c];
        float4 v3 = x4[(size_t)s3 * C4 + c];
        a0.x += v0.x; a0.y += v0.y; a0.z += v0.z; a0.w += v0.w;
        a1.x += v1.x; a1.y += v1.y; a1.z += v1.z; a1.w += v1.w;
        a2.x += v2.x; a2.y += v2.y; a2.z += v2.z; a2.w += v2.w;
        a3.x += v3.x; a3.y += v3.y; a3.z += v3.z; a3.w += v3.w;
    }
    for (; i < e; i++) {
        float4 v = x4[(size_t)srcs[i] * C4 + c];
        a0.x += v.x; a0.y += v.y; a0.z += v.z; a0.w += v.w;
    }
    a0.x += a1.x + a2.x + a3.x;
    a0.y += a1.y + a2.y + a3.y;
    a0.z += a1.z + a2.z + a3.z;
    a0.w += a1.w + a2.w + a3.w;
    agg4[(size_t)node * C4 + c] = a0;
}

// ---------------------------------------------------------------------------
// Tensor-core fused dual GEMM + bias + ELU (3xTF32, raw-fp32 smem,
// double-buffered, 1 sync per K-tile, cvt overlapped with MMA)
// ---------------------------------------------------------------------------
#define BM 128
#define BN 64
#define BK 16
#define ASTR 136   // stride%32==8 -> frag banks 8*lanek+lane4, conflict-free
#define BSTR 72

__device__ __forceinline__ uint32_t f2tf32(float x)
{
    uint32_t r;
    asm("cvt.rna.tf32.f32 %0, %1;" : "=r"(r) : "f"(x));
    return r;
}

__device__ __forceinline__ void mma_tf32(float* d, const uint32_t* a, const uint32_t* b)
{
    asm("mma.sync.aligned.m16n8k8.row.col.f32.tf32.tf32.f32 "
        "{%0,%1,%2,%3}, {%4,%5,%6,%7}, {%8,%9}, {%0,%1,%2,%3};\n"
        : "+f"(d[0]), "+f"(d[1]), "+f"(d[2]), "+f"(d[3])
        : "r"(a[0]), "r"(a[1]), "r"(a[2]), "r"(a[3]), "r"(b[0]), "r"(b[1]));
}

__global__ __launch_bounds__(256)
void gemm_dual_elu(const float* __restrict__ A1, const float* __restrict__ A2,
                   const float* __restrict__ W1, const float* __restrict__ W2,
                   const float* __restrict__ bias, float* __restrict__ out,
                   int N, int C, int CO)
{
    __shared__ float As[2][BK][ASTR];
    __shared__ float Bs[2][BK][BSTR];

    const int tid  = threadIdx.x;
    const int row0 = blockIdx.x * BM;
    const int col0 = blockIdx.y * BN;

    const int ar = tid & 127;
    const int ak = (tid >> 7) << 3;         // 0 or 8
    const int br = tid & 63;
    const int bk = ((tid >> 6) & 3) << 2;   // 0,4,8,12

    const int ga_row = row0 + ar;
    const int gb_row = col0 + br;

    const int w      = tid >> 5;
    const int lane   = tid & 31;
    const int lane4  = lane >> 2;
    const int lanek  = lane & 3;
    const int warp_m = (w & 3) * 32;
    const int warp_n = (w >> 2) * 32;

    float acc[2][4][4];
#pragma unroll
    for (int mt = 0; mt < 2; mt++)
#pragma unroll
        for (int nt = 0; nt < 4; nt++)
#pragma unroll
            for (int r = 0; r < 4; r++) acc[mt][nt][r] = 0.f;

    const int Ktot = 2 * C;
    const int nk   = Ktot / BK;

    float4 av0, av1, bv;

    // tile 0 -> regs -> smem[0]
    av0 = make_float4(0.f, 0.f, 0.f, 0.f); av1 = av0;
    if (ga_row < N) {
        av0 = *(const float4*)(A1 + (size_t)ga_row * C + ak);
        av1 = *(const float4*)(A1 + (size_t)ga_row * C + ak + 4);
    }
    bv = *(const float4*)(W1 + (size_t)gb_row * C + bk);

    {
        float af[8] = {av0.x, av0.y, av0.z, av0.w, av1.x, av1.y, av1.z, av1.w};
#pragma unroll
        for (int j = 0; j < 8; j++) As[0][ak + j][ar] = af[j];
        float bf[4] = {bv.x, bv.y, bv.z, bv.w};
#pragma unroll
        for (int j = 0; j < 4; j++) Bs[0][bk + j][br] = bf[j];
    }
    __syncthreads();

    int buf = 0;
    for (int t = 0; t < nk; t++) {
        // prefetch next tile (global -> regs), overlaps compute below
        if (t + 1 < nk) {
            int kt = (t + 1) * BK;
            const float* A; const float* W; int kb;
            if (kt < C) { A = A1; W = W1; kb = kt; }
            else        { A = A2; W = W2; kb = kt - C; }
            av0 = make_float4(0.f, 0.f, 0.f, 0.f); av1 = av0;
            if (ga_row < N) {
                av0 = *(const float4*)(A + (size_t)ga_row * C + kb + ak);
                av1 = *(const float4*)(A + (size_t)ga_row * C + kb + ak + 4);
            }
            bv = *(const float4*)(W + (size_t)gb_row * C + kb + bk);
        }

        // compute current buffer (cvt in regs, overlapped with tensor pipe)
#pragma unroll
        for (int ks = 0; ks < 2; ks++) {
            const int kk = ks * 8 + lanek;
            uint32_t aH[2][4], aL[2][4], bH[4][2], bL[4][2];
#pragma unroll
            for (int mt = 0; mt < 2; mt++) {
                int m = warp_m + mt * 16 + lane4;
                float r0 = As[buf][kk][m];
                float r1 = As[buf][kk][m + 8];
                float r2 = As[buf][kk + 4][m];
                float r3 = As[buf][kk + 4][m + 8];
                aH[mt][0] = f2tf32(r0); aL[mt][0] = f2tf32(r0 - __uint_as_float(aH[mt][0]));
                aH[mt][1] = f2tf32(r1); aL[mt][1] = f2tf32(r1 - __uint_as_float(aH[mt][1]));
                aH[mt][2] = f2tf32(r2); aL[mt][2] = f2tf32(r2 - __uint_as_float(aH[mt][2]));
                aH[mt][3] = f2tf32(r3); aL[mt][3] = f2tf32(r3 - __uint_as_float(aH[mt][3]));
            }
#pragma unroll
            for (int nt = 0; nt < 4; nt++) {
                int n = warp_n + nt * 8 + lane4;
                float r0 = Bs[buf][kk][n];
                float r1 = Bs[buf][kk + 4][n];
                bH[nt][0] = f2tf32(r0); bL[nt][0] = f2tf32(r0 - __uint_as_float(bH[nt][0]));
                bH[nt][1] = f2tf32(r1); bL[nt][1] = f2tf32(r1 - __uint_as_float(bH[nt][1]));
            }
#pragma unroll
            for (int mt = 0; mt < 2; mt++)
#pragma unroll
                for (int nt = 0; nt < 4; nt++) {
                    mma_tf32(acc[mt][nt], aL[mt], bH[nt]);
                    mma_tf32(acc[mt][nt], aH[mt], bL[nt]);
                    mma_tf32(acc[mt][nt], aH[mt], bH[nt]);
                }
        }

        // store next tile into the other buffer
        if (t + 1 < nk) {
            int nb2 = buf ^ 1;
            float af[8] = {av0.x, av0.y, av0.z, av0.w, av1.x, av1.y, av1.z, av1.w};
#pragma unroll
            for (int j = 0; j < 8; j++) As[nb2][ak + j][ar] = af[j];
            float bf[4] = {bv.x, bv.y, bv.z, bv.w};
#pragma unroll
            for (int j = 0; j < 4; j++) Bs[nb2][bk + j][br] = bf[j];
        }
        __syncthreads();
        buf ^= 1;
    }

    // epilogue: bias + ELU
#pragma unroll
    for (int nt = 0; nt < 4; nt++) {
        int c = col0 + warp_n + nt * 8 + lanek * 2;
        float b0f = bias[c];
        float b1f = bias[c + 1];
#pragma unroll
        for (int mt = 0; mt < 2; mt++) {
            int r0 = row0 + warp_m + mt * 16 + lane4;
            int r1 = r0 + 8;
            if (r0 < N) {
                float v0 = acc[mt][nt][0] + b0f;
                float v1 = acc[mt][nt][1] + b1f;
                v0 = v0 > 0.f ? v0 : expm1f(v0);
                v1 = v1 > 0.f ? v1 : expm1f(v1);
                *(float2*)(out + (size_t)r0 * CO + c) = make_float2(v0, v1);
            }
            if (r1 < N) {
                float v2 = acc[mt][nt][2] + b0f;
                float v3 = acc[mt][nt][3] + b1f;
                v2 = v2 > 0.f ? v2 : expm1f(v2);
                v3 = v3 > 0.f ? v3 : expm1f(v3);
                *(float2*)(out + (size_t)r1 * CO + c) = make_float2(v2, v3);
            }
        }
    }
}

// ---------------------------------------------------------------------------
// Segmented mean-pool (batch is SORTED): register accumulation, boundary-only
// atomics; fused node count. blockDim = 192 (one thread per channel).
// ---------------------------------------------------------------------------
#define POOL_NODES 256
__global__ __launch_bounds__(192)
void pool_seg_kernel(const float* __restrict__ x, const int* __restrict__ batch,
                     float* __restrict__ sums, float* __restrict__ cnt, int N)
{
    int c  = threadIdx.x;
    int n0 = blockIdx.x * POOL_NODES;
    if (n0 >= N) return;
    int n1 = n0 + POOL_NODES; if (n1 > N) n1 = N;

    int   cur = batch[n0];
    float acc = 0.f;
    int   m   = 0;
    for (int n = n0; n < n1; n++) {
        int b = batch[n];
        if (b != cur) {
            atomicAdd(&sums[cur * 192 + c], acc);
            if (c == 0) atomicAdd(&cnt[cur], (float)m);
            acc = 0.f; m = 0; cur = b;
        }
        acc += x[(size_t)n * 192 + c];
        m++;
    }
    atomicAdd(&sums[cur * 192 + c], acc);
    if (c == 0) atomicAdd(&cnt[cur], (float)m);
}

// ---------------------------------------------------------------------------
// Fused tail: cat + fc1(relu) + fc2(relu) + fc3. Single block, 1024 threads.
// ---------------------------------------------------------------------------
__global__ __launch_bounds__(1024)
void mlp_tail_kernel(const float* __restrict__ pool, const float* __restrict__ cnt,
                     const float* __restrict__ point,
                     const float* __restrict__ l1W, const float* __restrict__ l1b,
                     const float* __restrict__ l2W, const float* __restrict__ l2b,
                     const float* __restrict__ l3W, const float* __restrict__ l3b,
                     float* __restrict__ out)
{
    __shared__ float cat[NB * 448];
    __shared__ float h1 [NB * 600];
    __shared__ float h2 [NB * 256];
    int tid = threadIdx.x;

    for (int i = tid; i < NB * 448; i += 1024) {
        int b = i / 448, c = i - b * 448;
        float v;
        if (c < 192)      v = pool[b * 192 + c] / fmaxf(cnt[b], 1.f);
        else if (c < 384) v = pool[NB * 192 + b * 192 + (c - 192)] / fmaxf(cnt[NB + b], 1.f);
        else              v = point[b * NF + (c - 384)];
        cat[i] = v;
    }
    __syncthreads();

    int warp = tid >> 5, lane = tid & 31;

    for (int idx = warp; idx < NB * 600; idx += 32) {
        int b = idx / 600, o = idx - b * 600;
        float s = 0.f;
        for (int k = lane; k < 448; k += 32) s += cat[b * 448 + k] * l1W[o * 448 + k];
#pragma unroll
        for (int off = 16; off; off >>= 1) s += __shfl_xor_sync(0xFFFFFFFFu, s, off);
        if (lane == 0) h1[b * 600 + o] = fmaxf(s + l1b[o], 0.f);
    }
    __syncthreads();

    for (int idx = warp; idx < NB * 256; idx += 32) {
        int b = idx >> 8, o = idx & 255;
        float s = 0.f;
        for (int k = lane; k < 600; k += 32) s += h1[b * 600 + k] * l2W[o * 600 + k];
#pragma unroll
        for (int off = 16; off; off >>= 1) s += __shfl_xor_sync(0xFFFFFFFFu, s, off);
        if (lane == 0) h2[b * 256 + o] = fmaxf(s + l2b[o], 0.f);
    }
    __syncthreads();

    for (int idx = warp; idx < NB * 64; idx += 32) {
        int b = idx >> 6, o = idx & 63;
        float s = 0.f;
        for (int k = lane; k < 256; k += 32) s += h2[b * 256 + k] * l3W[o * 256 + k];
#pragma unroll
        for (int off = 16; off; off >>= 1) s += __shfl_xor_sync(0xFFFFFFFFu, s, off);
        if (lane == 0) out[b * 64 + o] = s + l3b[o];
    }
}

// ---------------------------------------------------------------------------
// Host-side branch driver
// ---------------------------------------------------------------------------
static void run_branch(const float* x_in, const int* ei, const int* batch,
                       int N, int E,
                       const float* W1r, const float* W1n, const float* B1,
                       const float* W2r, const float* W2n, const float* B2,
                       const float* W3r, const float* W3n, const float* B3,
                       float* buf0, float* buf1, float* agg,
                       int* rowptr, int* cursor, int* srcs, int* bsums,
                       float* sums, float* cnt)
{
    const int* src = ei;
    const int* dst = ei + E;

    cudaMemsetAsync(rowptr, 0, (size_t)(N + 1) * sizeof(int));
    hist_kernel<<<(E + 255) / 256, 256>>>(dst, rowptr, E);
    int nb = (N + 255) / 256;
    scan1_kernel<<<nb, 256>>>(rowptr, bsums, N);
    scan2_kernel<<<1, 256>>>(bsums, nb, rowptr, N, E);
    scan3_kernel<<<nb, 256>>>(rowptr, bsums, cursor, N);
    fill_kernel<<<(E + 255) / 256, 256>>>(src, dst, cursor, srcs, E);

    // L1: C=64 -> CO=128
    gather_kernel<<<(N + 15) / 16, 256>>>((const float4*)x_in, rowptr, srcs,
                                          (float4*)agg, N, 16, 4);
    gemm_dual_elu<<<dim3((N + BM - 1) / BM, 128 / BN), 256>>>(agg, x_in, W1r, W1n, B1, buf0, N, 64, 128);
    // L2: C=128 -> CO=256
    gather_kernel<<<(N + 7) / 8, 256>>>((const float4*)buf0, rowptr, srcs,
                                        (float4*)agg, N, 32, 5);
    gemm_dual_elu<<<dim3((N + BM - 1) / BM, 256 / BN), 256>>>(agg, buf0, W2r, W2n, B2, buf1, N, 128, 256);
    // L3: C=256 -> CO=192
    gather_kernel<<<(N + 3) / 4, 256>>>((const float4*)buf1, rowptr, srcs,
                                        (float4*)agg, N, 64, 6);
    gemm_dual_elu<<<dim3((N + BM - 1) / BM, 192 / BN), 256>>>(agg, buf1, W3r, W3n, B3, buf0, N, 256, 192);

    pool_seg_kernel<<<(N + POOL_NODES - 1) / POOL_NODES, 192>>>(buf0, batch, sums, cnt, N);
}

// ---------------------------------------------------------------------------
// kernel_launch
// ---------------------------------------------------------------------------
extern "C" void kernel_launch(void* const* d_in, const int* in_sizes, int n_in,
                              void* d_out, int out_size)
{
    int IDX[31];
    bool dict_order = (in_sizes[3] == 2 * E_G);
    if (dict_order) {
        int m[31] = {0,1,2, 7,8,9,10,11,12,13,14,15, 16,17,18,19,20,21,22,23,24,
                     25,26,27,28,29,30, 3,4,5,6};
        for (int i = 0; i < 31; i++) IDX[i] = m[i];
    } else {
        for (int i = 0; i < 31; i++) IDX[i] = i;
    }
    const float* graph_x    = (const float*)d_in[IDX[0]];
    const float* subgraph_x = (const float*)d_in[IDX[1]];
    const float* point      = (const float*)d_in[IDX[2]];
    const float* gW[9]; const float* sW[9];
    for (int i = 0; i < 9; i++) gW[i] = (const float*)d_in[IDX[3 + i]];
    for (int i = 0; i < 9; i++) sW[i] = (const float*)d_in[IDX[12 + i]];
    const float* l1W = (const float*)d_in[IDX[21]];
    const float* l1b = (const float*)d_in[IDX[22]];
    const float* l2W = (const float*)d_in[IDX[23]];
    const float* l2b = (const float*)d_in[IDX[24]];
    const float* l3W = (const float*)d_in[IDX[25]];
    const float* l3b = (const float*)d_in[IDX[26]];
    const int* g_ei   = (const int*)d_in[IDX[27]];
    const int* g_bat  = (const int*)d_in[IDX[28]];
    const int* s_ei   = (const int*)d_in[IDX[29]];
    const int* s_bat  = (const int*)d_in[IDX[30]];

    float *buf0, *buf1, *agg, *pool, *cnt;
    int *rowptr, *cursor, *srcs, *bsums;
    cudaGetSymbolAddress((void**)&buf0, g_buf0);
    cudaGetSymbolAddress((void**)&buf1, g_buf1);
    cudaGetSymbolAddress((void**)&agg,  g_agg);
    cudaGetSymbolAddress((void**)&pool, g_pool);
    cudaGetSymbolAddress((void**)&cnt,  g_cnt);
    cudaGetSymbolAddress((void**)&rowptr, g_rowptr);
    cudaGetSymbolAddress((void**)&cursor, g_cursor);
    cudaGetSymbolAddress((void**)&srcs,   g_srcs);
    cudaGetSymbolAddress((void**)&bsums,  g_bsums);

    float* out = (float*)d_out;

    cudaMemsetAsync(pool, 0, 2 * NB * 192 * sizeof(float));
    cudaMemsetAsync(cnt,  0, 2 * NB * sizeof(float));

    run_branch(graph_x, g_ei, g_bat, N_G, E_G,
               gW[0], gW[1], gW[2], gW[3], gW[4], gW[5], gW[6], gW[7], gW[8],
               buf0, buf1, agg, rowptr, cursor, srcs, bsums, pool, cnt);
    run_branch(subgraph_x, s_ei, s_bat, N_S, E_S,
               sW[0], sW[1], sW[2], sW[3], sW[4], sW[5], sW[6], sW[7], sW[8],
               buf0, buf1, agg, rowptr, cursor, srcs, bsums, pool + NB * 192, cnt + NB);

    mlp_tail_kernel<<<1, 1024>>>(pool, cnt, point, l1W, l1b, l2W, l2b, l3W, l3b, out);
    (void)n_in; (void)out_size;
}

// round 7
// speedup vs baseline: 1.0835x; 1.0835x over previous
#include <cuda_runtime.h>
#include <cuda_bf16.h>
#include <math.h>
#include <stdint.h>

#define N_G 50000
#define E_G 800000
#define N_S 10000
#define E_S 160000
#define NF 64
#define NB 8

// ---------------------------------------------------------------------------
// Scratch (device globals; allocation-free)
// ---------------------------------------------------------------------------
__device__ float g_buf0[(size_t)N_G * 256];
__device__ float g_buf1[(size_t)N_G * 256];
__device__ float g_agg [(size_t)N_G * 256];
__device__ float g_pool[2 * NB * 192];
__device__ float g_cnt [2 * NB];
__device__ int   g_rowptr[N_G + 1];
__device__ int   g_cursor[N_G];
__device__ int   g_srcs  [E_G];

// ---------------------------------------------------------------------------
// CSR build
// ---------------------------------------------------------------------------
__global__ void hist_kernel(const int* __restrict__ dst, int* __restrict__ counts, int E)
{
    int e = blockIdx.x * blockDim.x + threadIdx.x;
    if (e < E) atomicAdd(&counts[dst[e]], 1);
}

// single-block exclusive scan over counts -> rowptr (in place) + cursor init
__global__ __launch_bounds__(1024)
void scan_single_kernel(int* __restrict__ rowptr, int* __restrict__ cursor, int N, int E)
{
    __shared__ int tot[1024];
    int t   = threadIdx.x;
    int per = (N + 1023) / 1024;
    int b0  = t * per;
    int b1  = b0 + per; if (b1 > N) b1 = N; if (b0 > N) b0 = N;
    int s = 0;
    for (int i = b0; i < b1; i++) s += rowptr[i];
    tot[t] = s;
    __syncthreads();
    for (int off = 1; off < 1024; off <<= 1) {
        int v = (t >= off) ? tot[t - off] : 0;
        __syncthreads();
        tot[t] += v;
        __syncthreads();
    }
    int run = (t > 0) ? tot[t - 1] : 0;
    for (int i = b0; i < b1; i++) {
        int c = rowptr[i];
        rowptr[i] = run;
        cursor[i] = run;
        run += c;
    }
    if (t == 0) rowptr[N] = E;
}

__global__ void fill_kernel(const int* __restrict__ src, const int* __restrict__ dst,
                            int* __restrict__ cursor, int* __restrict__ srcs, int E)
{
    int e = blockIdx.x * blockDim.x + threadIdx.x;
    if (e >= E) return;
    int d = dst[e];
    int p = atomicAdd(&cursor[d], 1);
    srcs[p] = src[e];
}

// ---------------------------------------------------------------------------
// CSR gather aggregation (float4, 4-way unroll)
// ---------------------------------------------------------------------------
__global__ __launch_bounds__(256)
void gather_kernel(const float4* __restrict__ x4, const int* __restrict__ rowptr,
                   const int* __restrict__ srcs, float4* __restrict__ agg4,
                   int N, int C4, int lgC4)
{
    int c    = threadIdx.x & (C4 - 1);
    int node = blockIdx.x * (256 >> lgC4) + (threadIdx.x >> lgC4);
    if (node >= N) return;
    int b = rowptr[node];
    int e = rowptr[node + 1];
    float4 a0 = make_float4(0.f, 0.f, 0.f, 0.f);
    float4 a1 = a0, a2 = a0, a3 = a0;
    int i = b;
    for (; i + 4 <= e; i += 4) {
        int s0 = srcs[i], s1 = srcs[i + 1], s2 = srcs[i + 2], s3 = srcs[i + 3];
        float4 v0 = x4[(size_t)s0 * C4 + c];
        float4 v1 = x4[(size_t)s1 * C4 + c];
        float4 v2 = x4[(size_t)s2 * C4 + c];
        float4 v3 = x4[(size_t)s3 * C4 + c];
        a0.x += v0.x; a0.y += v0.y; a0.z += v0.z; a0.w += v0.w;
        a1.x += v1.x; a1.y += v1.y; a1.z += v1.z; a1.w += v1.w;
        a2.x += v2.x; a2.y += v2.y; a2.z += v2.z; a2.w += v2.w;
        a3.x += v3.x; a3.y += v3.y; a3.z += v3.z; a3.w += v3.w;
    }
    for (; i < e; i++) {
        float4 v = x4[(size_t)srcs[i] * C4 + c];
        a0.x += v.x; a0.y += v.y; a0.z += v.z; a0.w += v.w;
    }
    a0.x += a1.x + a2.x + a3.x;
    a0.y += a1.y + a2.y + a3.y;
    a0.z += a1.z + a2.z + a3.z;
    a0.w += a1.w + a2.w + a3.w;
    agg4[(size_t)node * C4 + c] = a0;
}

// ---------------------------------------------------------------------------
// 3xBF16 tensor-core fused dual GEMM + bias + ELU:
//   out[N][CO] = elu(A1 @ W1^T + A2 @ W2^T + bias)
// mma.sync.m16n8k16.bf16 (4096 FLOP/instr, 2x the tf32-k8 rate).
// Block tile 128x64, BK=32 (2 k16 steps), 256 threads = 8 warps (4m x 2n),
// warp tile 32x32. bf16 hi/lo split at load time, double-buffered smem,
// one __syncthreads per K-tile.
// smem words (uint32, each = packed bf16x2 of two consecutive k):
//   AH[2][16][136], AL[2][16][136], BH[2][16][72], BL[2][16][72]
// stride%32==8 keeps fragment LDS conflict-free (same pattern as validated
// round-3 tf32 kernel; identical reg->(row,k) mapping).
// ---------------------------------------------------------------------------
#define BM 128
#define BN 64
#define ASTR 136
#define BSTR 72
#define A_BUF (16 * ASTR)          // 2176 words per buffer
#define B_BUF (16 * BSTR)          // 1152 words per buffer
#define OFF_AH 0
#define OFF_AL (2 * A_BUF)         // 4352
#define OFF_BH (4 * A_BUF)         // 8704
#define OFF_BL (4 * A_BUF + 2 * B_BUF)  // 11008
#define GEMM_SMEM ((4 * A_BUF + 4 * B_BUF) * 4)   // 53248 bytes

__device__ __forceinline__ uint32_t bf2pack(float f0, float f1)
{
    __nv_bfloat162 h = __floats2bfloat162_rn(f0, f1);   // .x=f0 (low), .y=f1 (high)
    return reinterpret_cast<uint32_t&>(h);
}

__device__ __forceinline__ void split_pair(float f0, float f1, uint32_t& hi, uint32_t& lo)
{
    __nv_bfloat162 h = __floats2bfloat162_rn(f0, f1);
    float r0 = f0 - __bfloat162float(h.x);
    float r1 = f1 - __bfloat162float(h.y);
    hi = reinterpret_cast<uint32_t&>(h);
    lo = bf2pack(r0, r1);
}

__device__ __forceinline__ void mma_bf16(float* d, const uint32_t* a, const uint32_t* b)
{
    asm("mma.sync.aligned.m16n8k16.row.col.f32.bf16.bf16.f32 "
        "{%0,%1,%2,%3}, {%4,%5,%6,%7}, {%8,%9}, {%0,%1,%2,%3};\n"
        : "+f"(d[0]), "+f"(d[1]), "+f"(d[2]), "+f"(d[3])
        : "r"(a[0]), "r"(a[1]), "r"(a[2]), "r"(a[3]), "r"(b[0]), "r"(b[1]));
}

__global__ __launch_bounds__(256)
void gemm_bf16_elu(const float* __restrict__ A1, const float* __restrict__ A2,
                   const float* __restrict__ W1, const float* __restrict__ W2,
                   const float* __restrict__ bias, float* __restrict__ out,
                   int N, int C, int CO)
{
    extern __shared__ uint32_t sm[];
    uint32_t* AH = sm + OFF_AH;
    uint32_t* AL = sm + OFF_AL;
    uint32_t* BH = sm + OFF_BH;
    uint32_t* BL = sm + OFF_BL;

    const int tid  = threadIdx.x;
    const int row0 = blockIdx.x * BM;
    const int col0 = blockIdx.y * BN;

    // loader mapping: A 128x32 f32 -> 16 f32/thread; B 64x32 -> 8 f32/thread
    const int ar = tid >> 1;               // A row 0..127
    const int ak = (tid & 1) << 4;         // A k offset 0/16
    const int aw = ak >> 1;                // word base 0/8
    const int br = tid & 63;               // B row
    const int bk = ((tid >> 6) & 3) << 3;  // 0,8,16,24
    const int bw = bk >> 1;                // 0,4,8,12

    const int ga_row = row0 + ar;
    const int gb_row = col0 + br;          // always < CO

    // warp mapping
    const int w      = tid >> 5;
    const int lane   = tid & 31;
    const int lane4  = lane >> 2;
    const int lanek  = lane & 3;
    const int warp_m = (w & 3) * 32;
    const int warp_n = (w >> 2) * 32;

    float acc[2][4][4];
#pragma unroll
    for (int mt = 0; mt < 2; mt++)
#pragma unroll
        for (int nt = 0; nt < 4; nt++)
#pragma unroll
            for (int r = 0; r < 4; r++) acc[mt][nt][r] = 0.f;

    const int Ktot = 2 * C;
    const int nk   = Ktot >> 5;            // BK=32

    float4 av[4], bv[2];

    // tile 0 -> regs
    {
#pragma unroll
        for (int j = 0; j < 4; j++) {
            av[j] = make_float4(0.f, 0.f, 0.f, 0.f);
            if (ga_row < N) av[j] = *(const float4*)(A1 + (size_t)ga_row * C + ak + j * 4);
        }
#pragma unroll
        for (int j = 0; j < 2; j++)
            bv[j] = *(const float4*)(W1 + (size_t)gb_row * C + bk + j * 4);
    }
    // store tile 0
    {
#pragma unroll
        for (int j = 0; j < 4; j++) {
            uint32_t h0, l0, h1, l1;
            split_pair(av[j].x, av[j].y, h0, l0);
            split_pair(av[j].z, av[j].w, h1, l1);
            AH[(aw + j * 2) * ASTR + ar]     = h0;
            AL[(aw + j * 2) * ASTR + ar]     = l0;
            AH[(aw + j * 2 + 1) * ASTR + ar] = h1;
            AL[(aw + j * 2 + 1) * ASTR + ar] = l1;
        }
#pragma unroll
        for (int j = 0; j < 2; j++) {
            uint32_t h0, l0, h1, l1;
            split_pair(bv[j].x, bv[j].y, h0, l0);
            split_pair(bv[j].z, bv[j].w, h1, l1);
            BH[(bw + j * 2) * BSTR + br]     = h0;
            BL[(bw + j * 2) * BSTR + br]     = l0;
            BH[(bw + j * 2 + 1) * BSTR + br] = h1;
            BL[(bw + j * 2 + 1) * BSTR + br] = l1;
        }
    }
    __syncthreads();

    int buf = 0;
    for (int t = 0; t < nk; t++) {
        // prefetch next tile to regs (overlaps compute)
        if (t + 1 < nk) {
            int kt = (t + 1) << 5;
            const float* A; const float* W; int kb;
            if (kt < C) { A = A1; W = W1; kb = kt; }
            else        { A = A2; W = W2; kb = kt - C; }
#pragma unroll
            for (int j = 0; j < 4; j++) {
                av[j] = make_float4(0.f, 0.f, 0.f, 0.f);
                if (ga_row < N) av[j] = *(const float4*)(A + (size_t)ga_row * C + kb + ak + j * 4);
            }
#pragma unroll
            for (int j = 0; j < 2; j++)
                bv[j] = *(const float4*)(W + (size_t)gb_row * C + kb + bk + j * 4);
        }

        const uint32_t* ah = AH + buf * A_BUF;
        const uint32_t* al = AL + buf * A_BUF;
        const uint32_t* bh = BH + buf * B_BUF;
        const uint32_t* bl = BL + buf * B_BUF;

        // two k16 steps
#pragma unroll
        for (int ks = 0; ks < 2; ks++) {
            const int kwb = ks * 8 + lanek;
            uint32_t aHf[2][4], aLf[2][4], bHf[4][2], bLf[4][2];
#pragma unroll
            for (int mt = 0; mt < 2; mt++) {
                int m = warp_m + mt * 16 + lane4;
                aHf[mt][0] = ah[kwb * ASTR + m];
                aHf[mt][1] = ah[kwb * ASTR + m + 8];
                aHf[mt][2] = ah[(kwb + 4) * ASTR + m];
                aHf[mt][3] = ah[(kwb + 4) * ASTR + m + 8];
                aLf[mt][0] = al[kwb * ASTR + m];
                aLf[mt][1] = al[kwb * ASTR + m + 8];
                aLf[mt][2] = al[(kwb + 4) * ASTR + m];
                aLf[mt][3] = al[(kwb + 4) * ASTR + m + 8];
            }
#pragma unroll
            for (int nt = 0; nt < 4; nt++) {
                int n = warp_n + nt * 8 + lane4;
                bHf[nt][0] = bh[kwb * BSTR + n];
                bHf[nt][1] = bh[(kwb + 4) * BSTR + n];
                bLf[nt][0] = bl[kwb * BSTR + n];
                bLf[nt][1] = bl[(kwb + 4) * BSTR + n];
            }
#pragma unroll
            for (int mt = 0; mt < 2; mt++)
#pragma unroll
                for (int nt = 0; nt < 4; nt++) {
                    mma_bf16(acc[mt][nt], aLf[mt], bHf[nt]);
                    mma_bf16(acc[mt][nt], aHf[mt], bLf[nt]);
                    mma_bf16(acc[mt][nt], aHf[mt], bHf[nt]);
                }
        }

        // store next tile
        if (t + 1 < nk) {
            int nb = buf ^ 1;
            uint32_t* ah2 = AH + nb * A_BUF;
            uint32_t* al2 = AL + nb * A_BUF;
            uint32_t* bh2 = BH + nb * B_BUF;
            uint32_t* bl2 = BL + nb * B_BUF;
#pragma unroll
            for (int j = 0; j < 4; j++) {
                uint32_t h0, l0, h1, l1;
                split_pair(av[j].x, av[j].y, h0, l0);
                split_pair(av[j].z, av[j].w, h1, l1);
                ah2[(aw + j * 2) * ASTR + ar]     = h0;
                al2[(aw + j * 2) * ASTR + ar]     = l0;
                ah2[(aw + j * 2 + 1) * ASTR + ar] = h1;
                al2[(aw + j * 2 + 1) * ASTR + ar] = l1;
            }
#pragma unroll
            for (int j = 0; j < 2; j++) {
                uint32_t h0, l0, h1, l1;
                split_pair(bv[j].x, bv[j].y, h0, l0);
                split_pair(bv[j].z, bv[j].w, h1, l1);
                bh2[(bw + j * 2) * BSTR + br]     = h0;
                bl2[(bw + j * 2) * BSTR + br]     = l0;
                bh2[(bw + j * 2 + 1) * BSTR + br] = h1;
                bl2[(bw + j * 2 + 1) * BSTR + br] = l1;
            }
        }
        __syncthreads();
        buf ^= 1;
    }

    // epilogue: bias + ELU, float2 stores
#pragma unroll
    for (int nt = 0; nt < 4; nt++) {
        int c = col0 + warp_n + nt * 8 + lanek * 2;
        float b0f = bias[c];
        float b1f = bias[c + 1];
#pragma unroll
        for (int mt = 0; mt < 2; mt++) {
            int r0 = row0 + warp_m + mt * 16 + lane4;
            int r1 = r0 + 8;
            if (r0 < N) {
                float v0 = acc[mt][nt][0] + b0f;
                float v1 = acc[mt][nt][1] + b1f;
                v0 = v0 > 0.f ? v0 : expm1f(v0);
                v1 = v1 > 0.f ? v1 : expm1f(v1);
                *(float2*)(out + (size_t)r0 * CO + c) = make_float2(v0, v1);
            }
            if (r1 < N) {
                float v2 = acc[mt][nt][2] + b0f;
                float v3 = acc[mt][nt][3] + b1f;
                v2 = v2 > 0.f ? v2 : expm1f(v2);
                v3 = v3 > 0.f ? v3 : expm1f(v3);
                *(float2*)(out + (size_t)r1 * CO + c) = make_float2(v2, v3);
            }
        }
    }
}

// ---------------------------------------------------------------------------
// Segmented mean-pool (batch sorted): boundary-only atomics + fused count
// ---------------------------------------------------------------------------
#define POOL_NODES 256
__global__ __launch_bounds__(192)
void pool_seg_kernel(const float* __restrict__ x, const int* __restrict__ batch,
                     float* __restrict__ sums, float* __restrict__ cnt, int N)
{
    int c  = threadIdx.x;
    int n0 = blockIdx.x * POOL_NODES;
    if (n0 >= N) return;
    int n1 = n0 + POOL_NODES; if (n1 > N) n1 = N;

    int   cur = batch[n0];
    float acc = 0.f;
    int   m   = 0;
    for (int n = n0; n < n1; n++) {
        int b = batch[n];
        if (b != cur) {
            atomicAdd(&sums[cur * 192 + c], acc);
            if (c == 0) atomicAdd(&cnt[cur], (float)m);
            acc = 0.f; m = 0; cur = b;
        }
        acc += x[(size_t)n * 192 + c];
        m++;
    }
    atomicAdd(&sums[cur * 192 + c], acc);
    if (c == 0) atomicAdd(&cnt[cur], (float)m);
}

// ---------------------------------------------------------------------------
// Fused tail: cat + fc1(relu) + fc2(relu) + fc3. Single block, 1024 threads.
// ---------------------------------------------------------------------------
__global__ __launch_bounds__(1024)
void mlp_tail_kernel(const float* __restrict__ pool, const float* __restrict__ cnt,
                     const float* __restrict__ point,
                     const float* __restrict__ l1W, const float* __restrict__ l1b,
                     const float* __restrict__ l2W, const float* __restrict__ l2b,
                     const float* __restrict__ l3W, const float* __restrict__ l3b,
                     float* __restrict__ out)
{
    __shared__ float cat[NB * 448];
    __shared__ float h1 [NB * 600];
    __shared__ float h2 [NB * 256];
    int tid = threadIdx.x;

    for (int i = tid; i < NB * 448; i += 1024) {
        int b = i / 448, c = i - b * 448;
        float v;
        if (c < 192)      v = pool[b * 192 + c] / fmaxf(cnt[b], 1.f);
        else if (c < 384) v = pool[NB * 192 + b * 192 + (c - 192)] / fmaxf(cnt[NB + b], 1.f);
        else              v = point[b * NF + (c - 384)];
        cat[i] = v;
    }
    __syncthreads();

    int warp = tid >> 5, lane = tid & 31;

    for (int idx = warp; idx < NB * 600; idx += 32) {
        int b = idx / 600, o = idx - b * 600;
        float s = 0.f;
        for (int k = lane; k < 448; k += 32) s += cat[b * 448 + k] * l1W[o * 448 + k];
#pragma unroll
        for (int off = 16; off; off >>= 1) s += __shfl_xor_sync(0xFFFFFFFFu, s, off);
        if (lane == 0) h1[b * 600 + o] = fmaxf(s + l1b[o], 0.f);
    }
    __syncthreads();

    for (int idx = warp; idx < NB * 256; idx += 32) {
        int b = idx >> 8, o = idx & 255;
        float s = 0.f;
        for (int k = lane; k < 600; k += 32) s += h1[b * 600 + k] * l2W[o * 600 + k];
#pragma unroll
        for (int off = 16; off; off >>= 1) s += __shfl_xor_sync(0xFFFFFFFFu, s, off);
        if (lane == 0) h2[b * 256 + o] = fmaxf(s + l2b[o], 0.f);
    }
    __syncthreads();

    for (int idx = warp; idx < NB * 64; idx += 32) {
        int b = idx >> 6, o = idx & 63;
        float s = 0.f;
        for (int k = lane; k < 256; k += 32) s += h2[b * 256 + k] * l3W[o * 256 + k];
#pragma unroll
        for (int off = 16; off; off >>= 1) s += __shfl_xor_sync(0xFFFFFFFFu, s, off);
        if (lane == 0) out[b * 64 + o] = s + l3b[o];
    }
}

// ---------------------------------------------------------------------------
// Host-side branch driver
// ---------------------------------------------------------------------------
static void run_branch(const float* x_in, const int* ei, const int* batch,
                       int N, int E,
                       const float* W1r, const float* W1n, const float* B1,
                       const float* W2r, const float* W2n, const float* B2,
                       const float* W3r, const float* W3n, const float* B3,
                       float* buf0, float* buf1, float* agg,
                       int* rowptr, int* cursor, int* srcs)
{
    const int* src = ei;
    const int* dst = ei + E;

    cudaMemsetAsync(rowptr, 0, (size_t)(N + 1) * sizeof(int));
    hist_kernel<<<(E + 255) / 256, 256>>>(dst, rowptr, E);
    scan_single_kernel<<<1, 1024>>>(rowptr, cursor, N, E);
    fill_kernel<<<(E + 255) / 256, 256>>>(src, dst, cursor, srcs, E);

    int gx = (N + BM - 1) / BM;
    // L1: C=64 -> CO=128
    gather_kernel<<<(N + 15) / 16, 256>>>((const float4*)x_in, rowptr, srcs,
                                          (float4*)agg, N, 16, 4);
    gemm_bf16_elu<<<dim3(gx, 2), 256, GEMM_SMEM>>>(agg, x_in, W1r, W1n, B1, buf0, N, 64, 128);
    // L2: C=128 -> CO=256
    gather_kernel<<<(N + 7) / 8, 256>>>((const float4*)buf0, rowptr, srcs,
                                        (float4*)agg, N, 32, 5);
    gemm_bf16_elu<<<dim3(gx, 4), 256, GEMM_SMEM>>>(agg, buf0, W2r, W2n, B2, buf1, N, 128, 256);
    // L3: C=256 -> CO=192
    gather_kernel<<<(N + 3) / 4, 256>>>((const float4*)buf1, rowptr, srcs,
                                        (float4*)agg, N, 64, 6);
    gemm_bf16_elu<<<dim3(gx, 3), 256, GEMM_SMEM>>>(agg, buf1, W3r, W3n, B3, buf0, N, 256, 192);
}

// ---------------------------------------------------------------------------
// kernel_launch
// ---------------------------------------------------------------------------
extern "C" void kernel_launch(void* const* d_in, const int* in_sizes, int n_in,
                              void* d_out, int out_size)
{
    int IDX[31];
    bool dict_order = (in_sizes[3] == 2 * E_G);
    if (dict_order) {
        int m[31] = {0,1,2, 7,8,9,10,11,12,13,14,15, 16,17,18,19,20,21,22,23,24,
                     25,26,27,28,29,30, 3,4,5,6};
        for (int i = 0; i < 31; i++) IDX[i] = m[i];
    } else {
        for (int i = 0; i < 31; i++) IDX[i] = i;
    }
    const float* graph_x    = (const float*)d_in[IDX[0]];
    const float* subgraph_x = (const float*)d_in[IDX[1]];
    const float* point      = (const float*)d_in[IDX[2]];
    const float* gW[9]; const float* sW[9];
    for (int i = 0; i < 9; i++) gW[i] = (const float*)d_in[IDX[3 + i]];
    for (int i = 0; i < 9; i++) sW[i] = (const float*)d_in[IDX[12 + i]];
    const float* l1W = (const float*)d_in[IDX[21]];
    const float* l1b = (const float*)d_in[IDX[22]];
    const float* l2W = (const float*)d_in[IDX[23]];
    const float* l2b = (const float*)d_in[IDX[24]];
    const float* l3W = (const float*)d_in[IDX[25]];
    const float* l3b = (const float*)d_in[IDX[26]];
    const int* g_ei   = (const int*)d_in[IDX[27]];
    const int* g_bat  = (const int*)d_in[IDX[28]];
    const int* s_ei   = (const int*)d_in[IDX[29]];
    const int* s_bat  = (const int*)d_in[IDX[30]];

    float *buf0, *buf1, *agg, *pool, *cnt;
    int *rowptr, *cursor, *srcs;
    cudaGetSymbolAddress((void**)&buf0, g_buf0);
    cudaGetSymbolAddress((void**)&buf1, g_buf1);
    cudaGetSymbolAddress((void**)&agg,  g_agg);
    cudaGetSymbolAddress((void**)&pool, g_pool);
    cudaGetSymbolAddress((void**)&cnt,  g_cnt);
    cudaGetSymbolAddress((void**)&rowptr, g_rowptr);
    cudaGetSymbolAddress((void**)&cursor, g_cursor);
    cudaGetSymbolAddress((void**)&srcs,   g_srcs);

    cudaFuncSetAttribute(gemm_bf16_elu, cudaFuncAttributeMaxDynamicSharedMemorySize,
                         GEMM_SMEM);

    float* out = (float*)d_out;

    // Graph branch convs
    run_branch(graph_x, g_ei, g_bat, N_G, E_G,
               gW[0], gW[1], gW[2], gW[3], gW[4], gW[5], gW[6], gW[7], gW[8],
               buf0, buf1, agg, rowptr, cursor, srcs);
    // Pool init + graph pool
    cudaMemsetAsync(pool, 0, 2 * NB * 192 * sizeof(float));
    cudaMemsetAsync(cnt,  0, 2 * NB * sizeof(float));
    pool_seg_kernel<<<(N_G + POOL_NODES - 1) / POOL_NODES, 192>>>(buf0, g_bat, pool, cnt, N_G);

    // Subgraph branch convs + pool
    run_branch(subgraph_x, s_ei, s_bat, N_S, E_S,
               sW[0], sW[1], sW[2], sW[3], sW[4], sW[5], sW[6], sW[7], sW[8],
               buf0, buf1, agg, rowptr, cursor, srcs);
    pool_seg_kernel<<<(N_S + POOL_NODES - 1) / POOL_NODES, 192>>>(buf0, s_bat,
                                                                 pool + NB * 192, cnt + NB, N_S);

    mlp_tail_kernel<<<1, 1024>>>(pool, cnt, point, l1W, l1b, l2W, l2b, l3W, l3b, out);
    (void)n_in; (void)out_size;
}